// round 8
// baseline (speedup 1.0000x reference)
#include <cuda_runtime.h>
#include <cuda_bf16.h>

#define NUSERS 100000
#define NITEMS 200000
#define DIM    128
#define NEDGES 2000000
#define LN_EPS 1e-5f

#define NBUCKETS (NUSERS + NITEMS)
#define RSV_BLK 1024
#define NU_BLKS ((NUSERS + RSV_BLK - 1) / RSV_BLK)   // 98
#define NC_BLKS ((NITEMS + RSV_BLK - 1) / RSV_BLK)   // 196

// ---------------- scratch (device globals; no allocations allowed) ----------
// Device globals are zero-initialized at load. g_cnt/g_total rely on a
// self-restoring invariant: reserve re-zeroes g_cnt after reading, build
// re-zeroes g_total, so every kernel_launch call sees them zero.
__device__ __align__(16) float g_u_buf [NUSERS * DIM];   // layer-1 user out (fp32)
__device__ __align__(16) float g_i_buf [NITEMS * DIM];   // layer-1 item out (fp32)

// bf16 gather tables: row = 32 x uint2 (lane l holds dims 4l..4l+3)
__device__ __align__(16) uint2 g_u_bf0[NUSERS * 32];
__device__ __align__(16) uint2 g_i_bf0[NITEMS * 32];
__device__ __align__(16) uint2 g_u_bf1[NUSERS * 32];
__device__ __align__(16) uint2 g_i_bf1[NITEMS * 32];

// AoS edge lists sorted by bucket key: (other index, value-bits)
__device__ __align__(16) int2 g_by_r[NEDGES];
__device__ __align__(16) int2 g_by_c[NEDGES];

__device__ int g_cnt[NBUCKETS];    // histogram (zero on entry; restored by reserve)
__device__ int g_beg[NBUCKETS];    // per-bucket start
__device__ int g_cur[NBUCKETS];    // build cursors; after build = bucket end
__device__ int g_total[2];         // reservation counters (restored by build)

// ---------------- K1: bf16 conversion + histogram (fused) ---------------------
__global__ void prep_hist_kernel(const float4* __restrict__ u_src,
                                 const float4* __restrict__ i_src,
                                 const int* __restrict__ rows,
                                 const int* __restrict__ cols) {
    int idx = blockIdx.x * blockDim.x + threadIdx.x;
    if (idx < NUSERS * 32) {
        float4 v = __ldg(&u_src[idx]);
        __nv_bfloat162 lo = __float22bfloat162_rn(make_float2(v.x, v.y));
        __nv_bfloat162 hi = __float22bfloat162_rn(make_float2(v.z, v.w));
        uint2 o;
        o.x = *reinterpret_cast<unsigned int*>(&lo);
        o.y = *reinterpret_cast<unsigned int*>(&hi);
        g_u_bf0[idx] = o;
    }
    if (idx < NITEMS * 32) {
        float4 v = __ldg(&i_src[idx]);
        __nv_bfloat162 lo = __float22bfloat162_rn(make_float2(v.x, v.y));
        __nv_bfloat162 hi = __float22bfloat162_rn(make_float2(v.z, v.w));
        uint2 o;
        o.x = *reinterpret_cast<unsigned int*>(&lo);
        o.y = *reinterpret_cast<unsigned int*>(&hi);
        g_i_bf0[idx] = o;
    }
    if (idx < NEDGES) {
        atomicAdd(&g_cnt[__ldg(&rows[idx])], 1);
        atomicAdd(&g_cnt[NUSERS + __ldg(&cols[idx])], 1);
    }
}

// ---------------- K2: reservation scan; restores g_cnt=0 ----------------------
__global__ void reserve_kernel() {
    __shared__ int s[RSV_BLK];
    __shared__ int sbase;
    bool is_u = blockIdx.x < NU_BLKS;
    int first = is_u ? blockIdx.x * RSV_BLK
                     : NUSERS + (blockIdx.x - NU_BLKS) * RSV_BLK;
    int limit = is_u ? NUSERS : NBUCKETS;
    int t = threadIdx.x;
    int idx = first + t;
    int v = (idx < limit) ? g_cnt[idx] : 0;
    s[t] = v;
    __syncthreads();
    for (int o = 1; o < RSV_BLK; o <<= 1) {
        int x = (t >= o) ? s[t - o] : 0;
        __syncthreads();
        s[t] += x;
        __syncthreads();
    }
    if (t == RSV_BLK - 1) sbase = atomicAdd(&g_total[is_u ? 0 : 1], s[t]);
    __syncthreads();
    if (idx < limit) {
        int b = sbase + s[t] - v;
        g_beg[idx] = b;
        g_cur[idx] = b;
        g_cnt[idx] = 0;            // restore invariant
    }
}

// ---------------- K3: build AoS edge lists; restores g_total=0 -----------------
__global__ void build_kernel(const int* __restrict__ rows,
                             const int* __restrict__ cols,
                             const float* __restrict__ vals) {
    int e = blockIdx.x * blockDim.x + threadIdx.x;
    if (blockIdx.x == 0 && threadIdx.x < 2) g_total[threadIdx.x] = 0;
    if (e >= NEDGES) return;
    int r = rows[e];
    int c = cols[e];
    int vb = __float_as_int(vals[e]);
    int p1 = atomicAdd(&g_cur[r], 1);
    g_by_r[p1] = make_int2(c, vb);
    int p2 = atomicAdd(&g_cur[NUSERS + c], 1);
    g_by_c[p2] = make_int2(r, vb);
}

// ---------------- fused layer: smem-staged edges + 1 LDG.64 gather/edge --------
// Warp per destination row. Edge records are coalesce-loaded 32 at a time with
// ONE LDG.64 per lane, staged in smem, then consumed as LDS broadcasts.
// bf16 -> f32 unpack via shift/and (exact). All accumulation / LN in fp32.
template <bool WRITE_BF>
__global__ void __launch_bounds__(256) layer_kernel(
        const float4* __restrict__ self_u,
        const float4* __restrict__ self_i,
        const uint2*  __restrict__ bf_u,
        const uint2*  __restrict__ bf_i,
        const float*  __restrict__ gamma,
        const float*  __restrict__ beta,
        float4* __restrict__ out_u,
        float4* __restrict__ out_i,
        uint2*  __restrict__ outbf_u,
        uint2*  __restrict__ outbf_i) {
    __shared__ int2 s_edges[8][32];          // 8 warps x 32 staged edges
    int w    = (blockIdx.x * blockDim.x + threadIdx.x) >> 5;
    int wid  = (threadIdx.x >> 5);
    int lane = threadIdx.x & 31;
    if (w >= NUSERS + NITEMS) return;

    const float4* self4;
    const uint2*  other;
    const int2*   edges;
    float4*       out4;
    uint2*        outbf;
    int row;
    if (w < NUSERS) {
        row   = w;
        self4 = self_u;  other = bf_i;  edges = g_by_r;
        out4  = out_u;   outbf = outbf_u;
    } else {
        row   = w - NUSERS;
        self4 = self_i;  other = bf_u;  edges = g_by_c;
        out4  = out_i;   outbf = outbf_i;
    }
    int beg = __ldg(&g_beg[w]);
    int end = __ldg(&g_cur[w]);    // post-build cursor = bucket end

    float a0 = 0.f, a1 = 0.f, a2 = 0.f, a3 = 0.f;

    int p = beg;
    while (p < end) {
        int n = end - p;
        if (n > 32) n = 32;
        // stage up to 32 edge records with one coalesced LDG.64 per lane
        if (lane < n) s_edges[wid][lane] = __ldg(&edges[p + lane]);
        __syncwarp();
#pragma unroll 4
        for (int k = 0; k < n; k++) {
            int2 ek = s_edges[wid][k];               // LDS.64 broadcast
            float v = __int_as_float(ek.y);
            uint2 q = __ldg(&other[ek.x * 32 + lane]);  // 1 LDG.64 per edge
            float f0 = __uint_as_float(q.x << 16);
            float f1 = __uint_as_float(q.x & 0xFFFF0000u);
            float f2 = __uint_as_float(q.y << 16);
            float f3 = __uint_as_float(q.y & 0xFFFF0000u);
            a0 += v * f0;
            a1 += v * f1;
            a2 += v * f2;
            a3 += v * f3;
        }
        __syncwarp();
        p += n;
    }

    // residual (fp32, evict-first so bf16 tables keep L2)
    float4 r = __ldcs(&self4[row * 32 + lane]);
    a0 += r.x; a1 += r.y; a2 += r.z; a3 += r.w;

    // LayerNorm across the warp's 128 values
    float s  = a0 + a1 + a2 + a3;
    float sq = a0 * a0 + a1 * a1 + a2 * a2 + a3 * a3;
#pragma unroll
    for (int o = 16; o > 0; o >>= 1) {
        s  += __shfl_xor_sync(0xffffffffu, s,  o);
        sq += __shfl_xor_sync(0xffffffffu, sq, o);
    }
    float m    = s * (1.f / DIM);
    float var  = sq * (1.f / DIM) - m * m;
    float rstd = rsqrtf(var + LN_EPS);

    float4 g = __ldg(&reinterpret_cast<const float4*>(gamma)[lane]);
    float4 b = __ldg(&reinterpret_cast<const float4*>(beta )[lane]);

    float4 o;
    o.x = g.x * (a0 - m) * rstd + b.x;
    o.y = g.y * (a1 - m) * rstd + b.y;
    o.z = g.z * (a2 - m) * rstd + b.z;
    o.w = g.w * (a3 - m) * rstd + b.w;
    __stcs(&out4[row * 32 + lane], o);

    if (WRITE_BF) {
        __nv_bfloat162 lo = __float22bfloat162_rn(make_float2(o.x, o.y));
        __nv_bfloat162 hi = __float22bfloat162_rn(make_float2(o.z, o.w));
        uint2 ob;
        ob.x = *reinterpret_cast<unsigned int*>(&lo);
        ob.y = *reinterpret_cast<unsigned int*>(&hi);
        outbf[row * 32 + lane] = ob;
    }
}

// ---------------- launch -----------------------------------------------------
extern "C" void kernel_launch(void* const* d_in, const int* in_sizes, int n_in,
                              void* d_out, int out_size) {
    const float* user_emb = (const float*)d_in[0];
    const float* item_emb = (const float*)d_in[1];
    const float* vals     = (const float*)d_in[2];
    const float* gamma    = (const float*)d_in[3];
    const float* beta     = (const float*)d_in[4];
    const int*   rows     = (const int*)d_in[5];
    const int*   cols     = (const int*)d_in[6];

    float* out   = (float*)d_out;
    float* u_out = out;
    float* i_out = out + (size_t)NUSERS * DIM;

    void* p;
    cudaGetSymbolAddress(&p, g_u_buf);  float* u_buf = (float*)p;
    cudaGetSymbolAddress(&p, g_i_buf);  float* i_buf = (float*)p;
    cudaGetSymbolAddress(&p, g_u_bf0);  uint2* u_bf0 = (uint2*)p;
    cudaGetSymbolAddress(&p, g_i_bf0);  uint2* i_bf0 = (uint2*)p;
    cudaGetSymbolAddress(&p, g_u_bf1);  uint2* u_bf1 = (uint2*)p;
    cudaGetSymbolAddress(&p, g_i_bf1);  uint2* i_bf1 = (uint2*)p;

    const int prep_blocks  = (NITEMS * 32 + 255) / 256;              // 25000
    const int edge_blocks  = (NEDGES + 255) / 256;                   // 7813
    const int layer_blocks = ((NUSERS + NITEMS) * 32 + 255) / 256;   // 37500

    // 1: bf16 conversion + histogram
    prep_hist_kernel<<<prep_blocks, 256>>>((const float4*)user_emb,
                                           (const float4*)item_emb, rows, cols);
    // 2: reservation scan
    reserve_kernel<<<NU_BLKS + NC_BLKS, RSV_BLK>>>();
    // 3: build AoS edge lists
    build_kernel<<<edge_blocks, 256>>>(rows, cols, vals);

    // 4: layer 1 (profiled slot) — selves = originals, gathers from bf0
    layer_kernel<true><<<layer_blocks, 256>>>(
        (const float4*)user_emb, (const float4*)item_emb,
        u_bf0, i_bf0, gamma, beta,
        (float4*)u_buf, (float4*)i_buf, u_bf1, i_bf1);

    // 5: layer 2 — selves = layer-1 fp32, gathers from bf1, write final out
    layer_kernel<false><<<layer_blocks, 256>>>(
        (const float4*)u_buf, (const float4*)i_buf,
        u_bf1, i_bf1, gamma, beta,
        (float4*)u_out, (float4*)i_out, nullptr, nullptr);
}

// round 9
// speedup vs baseline: 1.1166x; 1.1166x over previous
#include <cuda_runtime.h>
#include <cuda_bf16.h>

#define NUSERS 100000
#define NITEMS 200000
#define DIM    128
#define NEDGES 2000000
#define LN_EPS 1e-5f

#define NBUCKETS (NUSERS + NITEMS)
#define RSV_BLK 1024
#define NU_BLKS ((NUSERS + RSV_BLK - 1) / RSV_BLK)   // 98
#define NC_BLKS ((NITEMS + RSV_BLK - 1) / RSV_BLK)   // 196

// ---------------- scratch (device globals; no allocations allowed) ----------
// Device globals are zero-initialized at load. g_cnt/g_total rely on a
// self-restoring invariant: reserve re-zeroes g_cnt after reading, build
// re-zeroes g_total, so every kernel_launch call sees them zero.
__device__ __align__(16) float g_u_buf [NUSERS * DIM];   // layer-1 user out (fp32)
__device__ __align__(16) float g_i_buf [NITEMS * DIM];   // layer-1 item out (fp32)

// bf16 gather tables: row = 32 x uint2 (lane l holds dims 4l..4l+3)
__device__ __align__(16) uint2 g_u_bf0[NUSERS * 32];
__device__ __align__(16) uint2 g_i_bf0[NITEMS * 32];
__device__ __align__(16) uint2 g_u_bf1[NUSERS * 32];
__device__ __align__(16) uint2 g_i_bf1[NITEMS * 32];

// AoS edge lists sorted by bucket key: (other index, value-bits)
__device__ __align__(16) int2 g_by_r[NEDGES];
__device__ __align__(16) int2 g_by_c[NEDGES];

__device__ int g_cnt[NBUCKETS];    // histogram (zero on entry; restored by reserve)
__device__ int g_beg[NBUCKETS];    // per-bucket start
__device__ int g_cur[NBUCKETS];    // build cursors; after build = bucket end
__device__ int g_total[2];         // reservation counters (restored by build)

// ---------------- K1: bf16 conversion + histogram (fused) ---------------------
__global__ void prep_hist_kernel(const float4* __restrict__ u_src,
                                 const float4* __restrict__ i_src,
                                 const int* __restrict__ rows,
                                 const int* __restrict__ cols) {
    int idx = blockIdx.x * blockDim.x + threadIdx.x;
    if (idx < NUSERS * 32) {
        float4 v = __ldg(&u_src[idx]);
        __nv_bfloat162 lo = __float22bfloat162_rn(make_float2(v.x, v.y));
        __nv_bfloat162 hi = __float22bfloat162_rn(make_float2(v.z, v.w));
        uint2 o;
        o.x = *reinterpret_cast<unsigned int*>(&lo);
        o.y = *reinterpret_cast<unsigned int*>(&hi);
        g_u_bf0[idx] = o;
    }
    if (idx < NITEMS * 32) {
        float4 v = __ldg(&i_src[idx]);
        __nv_bfloat162 lo = __float22bfloat162_rn(make_float2(v.x, v.y));
        __nv_bfloat162 hi = __float22bfloat162_rn(make_float2(v.z, v.w));
        uint2 o;
        o.x = *reinterpret_cast<unsigned int*>(&lo);
        o.y = *reinterpret_cast<unsigned int*>(&hi);
        g_i_bf0[idx] = o;
    }
    if (idx < NEDGES) {
        atomicAdd(&g_cnt[__ldg(&rows[idx])], 1);
        atomicAdd(&g_cnt[NUSERS + __ldg(&cols[idx])], 1);
    }
}

// ---------------- K2: reservation scan; restores g_cnt=0 ----------------------
__global__ void reserve_kernel() {
    __shared__ int s[RSV_BLK];
    __shared__ int sbase;
    bool is_u = blockIdx.x < NU_BLKS;
    int first = is_u ? blockIdx.x * RSV_BLK
                     : NUSERS + (blockIdx.x - NU_BLKS) * RSV_BLK;
    int limit = is_u ? NUSERS : NBUCKETS;
    int t = threadIdx.x;
    int idx = first + t;
    int v = (idx < limit) ? g_cnt[idx] : 0;
    s[t] = v;
    __syncthreads();
    for (int o = 1; o < RSV_BLK; o <<= 1) {
        int x = (t >= o) ? s[t - o] : 0;
        __syncthreads();
        s[t] += x;
        __syncthreads();
    }
    if (t == RSV_BLK - 1) sbase = atomicAdd(&g_total[is_u ? 0 : 1], s[t]);
    __syncthreads();
    if (idx < limit) {
        int b = sbase + s[t] - v;
        g_beg[idx] = b;
        g_cur[idx] = b;
        g_cnt[idx] = 0;            // restore invariant
    }
}

// ---------------- K3: build AoS edge lists; restores g_total=0 -----------------
__global__ void build_kernel(const int* __restrict__ rows,
                             const int* __restrict__ cols,
                             const float* __restrict__ vals) {
    int e = blockIdx.x * blockDim.x + threadIdx.x;
    if (blockIdx.x == 0 && threadIdx.x < 2) g_total[threadIdx.x] = 0;
    if (e >= NEDGES) return;
    int r = rows[e];
    int c = cols[e];
    int vb = __float_as_int(vals[e]);
    int p1 = atomicAdd(&g_cur[r], 1);
    g_by_r[p1] = make_int2(c, vb);
    int p2 = atomicAdd(&g_cur[NUSERS + c], 1);
    g_by_c[p2] = make_int2(r, vb);
}

// ---------------- fused layer: max-occupancy gather + residual + LN ------------
// Warp per destination row, 64 warps/SM (launch_bounds(256,8) -> <=32 regs).
// One LDG.64 gather per edge; bf16 -> f32 unpack via shift/and (exact).
template <bool WRITE_BF>
__global__ void __launch_bounds__(256, 8) layer_kernel(
        const float4* __restrict__ self_u,
        const float4* __restrict__ self_i,
        const uint2*  __restrict__ bf_u,
        const uint2*  __restrict__ bf_i,
        const float*  __restrict__ gamma,
        const float*  __restrict__ beta,
        float4* __restrict__ out_u,
        float4* __restrict__ out_i,
        uint2*  __restrict__ outbf_u,
        uint2*  __restrict__ outbf_i) {
    int w    = (blockIdx.x * blockDim.x + threadIdx.x) >> 5;
    int lane = threadIdx.x & 31;
    if (w >= NUSERS + NITEMS) return;

    const float4* self4;
    const uint2*  other;
    const int2*   edges;
    float4*       out4;
    uint2*        outbf;
    int row;
    if (w < NUSERS) {
        row   = w;
        self4 = self_u;  other = bf_i;  edges = g_by_r;
        out4  = out_u;   outbf = outbf_u;
    } else {
        row   = w - NUSERS;
        self4 = self_i;  other = bf_u;  edges = g_by_c;
        out4  = out_i;   outbf = outbf_i;
    }
    int p   = __ldg(&g_beg[w]);
    int end = __ldg(&g_cur[w]);    // post-build cursor = bucket end

    float a0 = 0.f, a1 = 0.f, a2 = 0.f, a3 = 0.f;

#pragma unroll 1
    for (; p + 4 <= end; p += 4) {
        int2 e0 = __ldg(&edges[p + 0]);
        int2 e1 = __ldg(&edges[p + 1]);
        int2 e2 = __ldg(&edges[p + 2]);
        int2 e3 = __ldg(&edges[p + 3]);
        uint2 q0 = __ldg(&other[e0.x * 32 + lane]);
        uint2 q1 = __ldg(&other[e1.x * 32 + lane]);
        uint2 q2 = __ldg(&other[e2.x * 32 + lane]);
        uint2 q3 = __ldg(&other[e3.x * 32 + lane]);
        float v0 = __int_as_float(e0.y);
        float v1 = __int_as_float(e1.y);
        float v2 = __int_as_float(e2.y);
        float v3 = __int_as_float(e3.y);
        a0 += v0 * __uint_as_float(q0.x << 16);
        a1 += v0 * __uint_as_float(q0.x & 0xFFFF0000u);
        a2 += v0 * __uint_as_float(q0.y << 16);
        a3 += v0 * __uint_as_float(q0.y & 0xFFFF0000u);
        a0 += v1 * __uint_as_float(q1.x << 16);
        a1 += v1 * __uint_as_float(q1.x & 0xFFFF0000u);
        a2 += v1 * __uint_as_float(q1.y << 16);
        a3 += v1 * __uint_as_float(q1.y & 0xFFFF0000u);
        a0 += v2 * __uint_as_float(q2.x << 16);
        a1 += v2 * __uint_as_float(q2.x & 0xFFFF0000u);
        a2 += v2 * __uint_as_float(q2.y << 16);
        a3 += v2 * __uint_as_float(q2.y & 0xFFFF0000u);
        a0 += v3 * __uint_as_float(q3.x << 16);
        a1 += v3 * __uint_as_float(q3.x & 0xFFFF0000u);
        a2 += v3 * __uint_as_float(q3.y << 16);
        a3 += v3 * __uint_as_float(q3.y & 0xFFFF0000u);
    }
#pragma unroll 1
    for (; p < end; p++) {
        int2 e0 = __ldg(&edges[p]);
        uint2 q0 = __ldg(&other[e0.x * 32 + lane]);
        float v0 = __int_as_float(e0.y);
        a0 += v0 * __uint_as_float(q0.x << 16);
        a1 += v0 * __uint_as_float(q0.x & 0xFFFF0000u);
        a2 += v0 * __uint_as_float(q0.y << 16);
        a3 += v0 * __uint_as_float(q0.y & 0xFFFF0000u);
    }

    // residual (fp32, evict-first so bf16 tables keep L2)
    float4 r = __ldcs(&self4[row * 32 + lane]);
    a0 += r.x; a1 += r.y; a2 += r.z; a3 += r.w;

    // LayerNorm across the warp's 128 values
    float s  = a0 + a1 + a2 + a3;
    float sq = a0 * a0 + a1 * a1 + a2 * a2 + a3 * a3;
#pragma unroll
    for (int o = 16; o > 0; o >>= 1) {
        s  += __shfl_xor_sync(0xffffffffu, s,  o);
        sq += __shfl_xor_sync(0xffffffffu, sq, o);
    }
    float m    = s * (1.f / DIM);
    float var  = sq * (1.f / DIM) - m * m;
    float rstd = rsqrtf(var + LN_EPS);

    float4 g = __ldg(&reinterpret_cast<const float4*>(gamma)[lane]);
    float4 b = __ldg(&reinterpret_cast<const float4*>(beta )[lane]);

    float4 o;
    o.x = g.x * (a0 - m) * rstd + b.x;
    o.y = g.y * (a1 - m) * rstd + b.y;
    o.z = g.z * (a2 - m) * rstd + b.z;
    o.w = g.w * (a3 - m) * rstd + b.w;
    __stcs(&out4[row * 32 + lane], o);

    if (WRITE_BF) {
        __nv_bfloat162 lo = __float22bfloat162_rn(make_float2(o.x, o.y));
        __nv_bfloat162 hi = __float22bfloat162_rn(make_float2(o.z, o.w));
        uint2 ob;
        ob.x = *reinterpret_cast<unsigned int*>(&lo);
        ob.y = *reinterpret_cast<unsigned int*>(&hi);
        outbf[row * 32 + lane] = ob;
    }
}

// ---------------- launch -----------------------------------------------------
extern "C" void kernel_launch(void* const* d_in, const int* in_sizes, int n_in,
                              void* d_out, int out_size) {
    const float* user_emb = (const float*)d_in[0];
    const float* item_emb = (const float*)d_in[1];
    const float* vals     = (const float*)d_in[2];
    const float* gamma    = (const float*)d_in[3];
    const float* beta     = (const float*)d_in[4];
    const int*   rows     = (const int*)d_in[5];
    const int*   cols     = (const int*)d_in[6];

    float* out   = (float*)d_out;
    float* u_out = out;
    float* i_out = out + (size_t)NUSERS * DIM;

    void* p;
    cudaGetSymbolAddress(&p, g_u_buf);  float* u_buf = (float*)p;
    cudaGetSymbolAddress(&p, g_i_buf);  float* i_buf = (float*)p;
    cudaGetSymbolAddress(&p, g_u_bf0);  uint2* u_bf0 = (uint2*)p;
    cudaGetSymbolAddress(&p, g_i_bf0);  uint2* i_bf0 = (uint2*)p;
    cudaGetSymbolAddress(&p, g_u_bf1);  uint2* u_bf1 = (uint2*)p;
    cudaGetSymbolAddress(&p, g_i_bf1);  uint2* i_bf1 = (uint2*)p;

    const int prep_blocks  = (NITEMS * 32 + 255) / 256;              // 25000
    const int edge_blocks  = (NEDGES + 255) / 256;                   // 7813
    const int layer_blocks = ((NUSERS + NITEMS) * 32 + 255) / 256;   // 37500

    // 1: bf16 conversion + histogram
    prep_hist_kernel<<<prep_blocks, 256>>>((const float4*)user_emb,
                                           (const float4*)item_emb, rows, cols);
    // 2: reservation scan
    reserve_kernel<<<NU_BLKS + NC_BLKS, RSV_BLK>>>();
    // 3: build AoS edge lists
    build_kernel<<<edge_blocks, 256>>>(rows, cols, vals);

    // 4: layer 1 (profiled slot) — selves = originals, gathers from bf0
    layer_kernel<true><<<layer_blocks, 256>>>(
        (const float4*)user_emb, (const float4*)item_emb,
        u_bf0, i_bf0, gamma, beta,
        (float4*)u_buf, (float4*)i_buf, u_bf1, i_bf1);

    // 5: layer 2 — selves = layer-1 fp32, gathers from bf1, write final out
    layer_kernel<false><<<layer_blocks, 256>>>(
        (const float4*)u_buf, (const float4*)i_buf,
        u_bf1, i_bf1, gamma, beta,
        (float4*)u_out, (float4*)i_out, nullptr, nullptr);
}

// round 10
// speedup vs baseline: 1.2160x; 1.0891x over previous
#include <cuda_runtime.h>
#include <cuda_bf16.h>

#define NUSERS 100000
#define NITEMS 200000
#define DIM    128
#define NEDGES 2000000
#define LN_EPS 1e-5f

#define NBUCKETS (NUSERS + NITEMS)
#define RSV_BLK 1024
#define NU_BLKS ((NUSERS + RSV_BLK - 1) / RSV_BLK)   // 98
#define NC_BLKS ((NITEMS + RSV_BLK - 1) / RSV_BLK)   // 196

// ---------------- scratch (device globals; no allocations allowed) ----------
// Device globals are zero-initialized at load. g_cnt/g_total rely on a
// self-restoring invariant: reserve re-zeroes g_cnt after reading, build
// re-zeroes g_total, so every kernel_launch call sees them zero.
__device__ __align__(16) float g_u_buf [NUSERS * DIM];   // layer-1 user out (fp32)
__device__ __align__(16) float g_i_buf [NITEMS * DIM];   // layer-1 item out (fp32)

// bf16 gather tables: row = 32 x uint2 (lane l holds dims 4l..4l+3)
__device__ __align__(16) uint2 g_u_bf0[NUSERS * 32];
__device__ __align__(16) uint2 g_i_bf0[NITEMS * 32];
__device__ __align__(16) uint2 g_u_bf1[NUSERS * 32];
__device__ __align__(16) uint2 g_i_bf1[NITEMS * 32];

// AoS edge lists sorted by bucket key: (other index, value-bits)
__device__ __align__(16) int2 g_by_r[NEDGES];
__device__ __align__(16) int2 g_by_c[NEDGES];

__device__ int g_cnt[NBUCKETS];    // histogram (zero on entry; restored by reserve)
__device__ int g_beg[NBUCKETS];    // per-bucket start
__device__ int g_cur[NBUCKETS];    // build cursors; after build = bucket end
__device__ int g_total[2];         // reservation counters (restored by build)

// ---------------- K1: bf16 conversion + histogram (fused) ---------------------
__global__ void prep_hist_kernel(const float4* __restrict__ u_src,
                                 const float4* __restrict__ i_src,
                                 const int* __restrict__ rows,
                                 const int* __restrict__ cols) {
    int idx = blockIdx.x * blockDim.x + threadIdx.x;
    if (idx < NUSERS * 32) {
        float4 v = __ldg(&u_src[idx]);
        __nv_bfloat162 lo = __float22bfloat162_rn(make_float2(v.x, v.y));
        __nv_bfloat162 hi = __float22bfloat162_rn(make_float2(v.z, v.w));
        uint2 o;
        o.x = *reinterpret_cast<unsigned int*>(&lo);
        o.y = *reinterpret_cast<unsigned int*>(&hi);
        g_u_bf0[idx] = o;
    }
    if (idx < NITEMS * 32) {
        float4 v = __ldg(&i_src[idx]);
        __nv_bfloat162 lo = __float22bfloat162_rn(make_float2(v.x, v.y));
        __nv_bfloat162 hi = __float22bfloat162_rn(make_float2(v.z, v.w));
        uint2 o;
        o.x = *reinterpret_cast<unsigned int*>(&lo);
        o.y = *reinterpret_cast<unsigned int*>(&hi);
        g_i_bf0[idx] = o;
    }
    if (idx < NEDGES) {
        atomicAdd(&g_cnt[__ldg(&rows[idx])], 1);
        atomicAdd(&g_cnt[NUSERS + __ldg(&cols[idx])], 1);
    }
}

// ---------------- K2: reservation scan; restores g_cnt=0 ----------------------
__global__ void reserve_kernel() {
    __shared__ int s[RSV_BLK];
    __shared__ int sbase;
    bool is_u = blockIdx.x < NU_BLKS;
    int first = is_u ? blockIdx.x * RSV_BLK
                     : NUSERS + (blockIdx.x - NU_BLKS) * RSV_BLK;
    int limit = is_u ? NUSERS : NBUCKETS;
    int t = threadIdx.x;
    int idx = first + t;
    int v = (idx < limit) ? g_cnt[idx] : 0;
    s[t] = v;
    __syncthreads();
    for (int o = 1; o < RSV_BLK; o <<= 1) {
        int x = (t >= o) ? s[t - o] : 0;
        __syncthreads();
        s[t] += x;
        __syncthreads();
    }
    if (t == RSV_BLK - 1) sbase = atomicAdd(&g_total[is_u ? 0 : 1], s[t]);
    __syncthreads();
    if (idx < limit) {
        int b = sbase + s[t] - v;
        g_beg[idx] = b;
        g_cur[idx] = b;
        g_cnt[idx] = 0;            // restore invariant
    }
}

// ---------------- K3: build AoS edge lists; restores g_total=0 -----------------
__global__ void build_kernel(const int* __restrict__ rows,
                             const int* __restrict__ cols,
                             const float* __restrict__ vals) {
    int e = blockIdx.x * blockDim.x + threadIdx.x;
    if (blockIdx.x == 0 && threadIdx.x < 2) g_total[threadIdx.x] = 0;
    if (e >= NEDGES) return;
    int r = rows[e];
    int c = cols[e];
    int vb = __float_as_int(vals[e]);
    int p1 = atomicAdd(&g_cur[r], 1);
    g_by_r[p1] = make_int2(c, vb);
    int p2 = atomicAdd(&g_cur[NUSERS + c], 1);
    g_by_c[p2] = make_int2(r, vb);
}

// ---------------- fused layer: 2-warp blocks, prefetched residual --------------
// Warp per destination row; 64-thread blocks shrink the block-retirement
// granule so degree imbalance wastes ~12% instead of ~35% of warp slots.
// 32 blocks/SM x 2 warps = 64 warps/SM (32-reg cap).
template <bool WRITE_BF>
__global__ void __launch_bounds__(64, 32) layer_kernel(
        const float4* __restrict__ self_u,
        const float4* __restrict__ self_i,
        const uint2*  __restrict__ bf_u,
        const uint2*  __restrict__ bf_i,
        const float*  __restrict__ gamma,
        const float*  __restrict__ beta,
        float4* __restrict__ out_u,
        float4* __restrict__ out_i,
        uint2*  __restrict__ outbf_u,
        uint2*  __restrict__ outbf_i) {
    int w    = (blockIdx.x * blockDim.x + threadIdx.x) >> 5;
    int lane = threadIdx.x & 31;
    if (w >= NUSERS + NITEMS) return;

    const float4* self4;
    const uint2*  other;
    const int2*   edges;
    float4*       out4;
    uint2*        outbf;
    int row;
    if (w < NUSERS) {
        row   = w;
        self4 = self_u;  other = bf_i;  edges = g_by_r;
        out4  = out_u;   outbf = outbf_u;
    } else {
        row   = w - NUSERS;
        self4 = self_i;  other = bf_u;  edges = g_by_c;
        out4  = out_i;   outbf = outbf_i;
    }
    int p   = __ldg(&g_beg[w]);
    int end = __ldg(&g_cur[w]);    // post-build cursor = bucket end

    // prefetch residual: overlap its DRAM latency with the gather loop
    float4 r = __ldcs(&self4[row * 32 + lane]);

    float a0 = 0.f, a1 = 0.f, a2 = 0.f, a3 = 0.f;

#pragma unroll 1
    for (; p + 4 <= end; p += 4) {
        int2 e0 = __ldg(&edges[p + 0]);
        int2 e1 = __ldg(&edges[p + 1]);
        int2 e2 = __ldg(&edges[p + 2]);
        int2 e3 = __ldg(&edges[p + 3]);
        uint2 q0 = __ldg(&other[e0.x * 32 + lane]);
        uint2 q1 = __ldg(&other[e1.x * 32 + lane]);
        uint2 q2 = __ldg(&other[e2.x * 32 + lane]);
        uint2 q3 = __ldg(&other[e3.x * 32 + lane]);
        float v0 = __int_as_float(e0.y);
        float v1 = __int_as_float(e1.y);
        float v2 = __int_as_float(e2.y);
        float v3 = __int_as_float(e3.y);
        a0 += v0 * __uint_as_float(q0.x << 16);
        a1 += v0 * __uint_as_float(q0.x & 0xFFFF0000u);
        a2 += v0 * __uint_as_float(q0.y << 16);
        a3 += v0 * __uint_as_float(q0.y & 0xFFFF0000u);
        a0 += v1 * __uint_as_float(q1.x << 16);
        a1 += v1 * __uint_as_float(q1.x & 0xFFFF0000u);
        a2 += v1 * __uint_as_float(q1.y << 16);
        a3 += v1 * __uint_as_float(q1.y & 0xFFFF0000u);
        a0 += v2 * __uint_as_float(q2.x << 16);
        a1 += v2 * __uint_as_float(q2.x & 0xFFFF0000u);
        a2 += v2 * __uint_as_float(q2.y << 16);
        a3 += v2 * __uint_as_float(q2.y & 0xFFFF0000u);
        a0 += v3 * __uint_as_float(q3.x << 16);
        a1 += v3 * __uint_as_float(q3.x & 0xFFFF0000u);
        a2 += v3 * __uint_as_float(q3.y << 16);
        a3 += v3 * __uint_as_float(q3.y & 0xFFFF0000u);
    }
#pragma unroll 1
    for (; p < end; p++) {
        int2 e0 = __ldg(&edges[p]);
        uint2 q0 = __ldg(&other[e0.x * 32 + lane]);
        float v0 = __int_as_float(e0.y);
        a0 += v0 * __uint_as_float(q0.x << 16);
        a1 += v0 * __uint_as_float(q0.x & 0xFFFF0000u);
        a2 += v0 * __uint_as_float(q0.y << 16);
        a3 += v0 * __uint_as_float(q0.y & 0xFFFF0000u);
    }

    // residual add
    a0 += r.x; a1 += r.y; a2 += r.z; a3 += r.w;

    // LayerNorm across the warp's 128 values
    float s  = a0 + a1 + a2 + a3;
    float sq = a0 * a0 + a1 * a1 + a2 * a2 + a3 * a3;
#pragma unroll
    for (int o = 16; o > 0; o >>= 1) {
        s  += __shfl_xor_sync(0xffffffffu, s,  o);
        sq += __shfl_xor_sync(0xffffffffu, sq, o);
    }
    float m    = s * (1.f / DIM);
    float var  = sq * (1.f / DIM) - m * m;
    float rstd = rsqrtf(var + LN_EPS);

    float4 g = __ldg(&reinterpret_cast<const float4*>(gamma)[lane]);
    float4 b = __ldg(&reinterpret_cast<const float4*>(beta )[lane]);

    float4 o;
    o.x = g.x * (a0 - m) * rstd + b.x;
    o.y = g.y * (a1 - m) * rstd + b.y;
    o.z = g.z * (a2 - m) * rstd + b.z;
    o.w = g.w * (a3 - m) * rstd + b.w;
    __stcs(&out4[row * 32 + lane], o);

    if (WRITE_BF) {
        __nv_bfloat162 lo = __float22bfloat162_rn(make_float2(o.x, o.y));
        __nv_bfloat162 hi = __float22bfloat162_rn(make_float2(o.z, o.w));
        uint2 ob;
        ob.x = *reinterpret_cast<unsigned int*>(&lo);
        ob.y = *reinterpret_cast<unsigned int*>(&hi);
        outbf[row * 32 + lane] = ob;
    }
}

// ---------------- launch -----------------------------------------------------
extern "C" void kernel_launch(void* const* d_in, const int* in_sizes, int n_in,
                              void* d_out, int out_size) {
    const float* user_emb = (const float*)d_in[0];
    const float* item_emb = (const float*)d_in[1];
    const float* vals     = (const float*)d_in[2];
    const float* gamma    = (const float*)d_in[3];
    const float* beta     = (const float*)d_in[4];
    const int*   rows     = (const int*)d_in[5];
    const int*   cols     = (const int*)d_in[6];

    float* out   = (float*)d_out;
    float* u_out = out;
    float* i_out = out + (size_t)NUSERS * DIM;

    void* p;
    cudaGetSymbolAddress(&p, g_u_buf);  float* u_buf = (float*)p;
    cudaGetSymbolAddress(&p, g_i_buf);  float* i_buf = (float*)p;
    cudaGetSymbolAddress(&p, g_u_bf0);  uint2* u_bf0 = (uint2*)p;
    cudaGetSymbolAddress(&p, g_i_bf0);  uint2* i_bf0 = (uint2*)p;
    cudaGetSymbolAddress(&p, g_u_bf1);  uint2* u_bf1 = (uint2*)p;
    cudaGetSymbolAddress(&p, g_i_bf1);  uint2* i_bf1 = (uint2*)p;

    const int prep_blocks  = (NITEMS * 32 + 255) / 256;              // 25000
    const int edge_blocks  = (NEDGES + 255) / 256;                   // 7813
    const int layer_blocks = ((NUSERS + NITEMS) * 2 + 1) / 2;        // 1 block = 2 rows
    const int layer_grid   = (NUSERS + NITEMS + 1) / 2;              // 150000

    (void)layer_blocks;

    // 1: bf16 conversion + histogram
    prep_hist_kernel<<<prep_blocks, 256>>>((const float4*)user_emb,
                                           (const float4*)item_emb, rows, cols);
    // 2: reservation scan
    reserve_kernel<<<NU_BLKS + NC_BLKS, RSV_BLK>>>();
    // 3: build AoS edge lists
    build_kernel<<<edge_blocks, 256>>>(rows, cols, vals);

    // 4: layer 1 (profiled slot) — selves = originals, gathers from bf0
    layer_kernel<true><<<layer_grid, 64>>>(
        (const float4*)user_emb, (const float4*)item_emb,
        u_bf0, i_bf0, gamma, beta,
        (float4*)u_buf, (float4*)i_buf, u_bf1, i_bf1);

    // 5: layer 2 — selves = layer-1 fp32, gathers from bf1, write final out
    layer_kernel<false><<<layer_grid, 64>>>(
        (const float4*)u_buf, (const float4*)i_buf,
        u_bf1, i_bf1, gamma, beta,
        (float4*)u_out, (float4*)i_out, nullptr, nullptr);
}